// round 12
// baseline (speedup 1.0000x reference)
#include <cuda_runtime.h>
#include <cuda_bf16.h>
#include <mma.h>
#include <stdint.h>

using namespace nvcuda;

// Loihi CUBA constants
#define AI 0.75f
#define AV 0.96875f
#define TH 100.0f

__device__ __forceinline__ void add2(unsigned long long& a, unsigned long long b) {
    asm("add.rn.f32x2 %0, %0, %1;" : "+l"(a) : "l"(b));
}
__device__ __forceinline__ float2 u64f2(unsigned long long v) {
    float2 f; asm("mov.b64 {%0, %1}, %2;" : "=f"(f.x), "=f"(f.y) : "l"(v)); return f;
}
__device__ __forceinline__ uint32_t expand2(uint32_t b) {
    return ((b & 1u) ? 0x3F80u : 0u) | ((b & 2u) ? 0x3F800000u : 0u);
}

// ---------------------------------------------------------------------------
// Buffers (bit k of word j = spike at t = j*32+k; all streams pre-delayed)
// ---------------------------------------------------------------------------
__device__ uint32_t g_s0[16 * 2  * 40 * 40 * 4];
__device__ uint32_t g_s1[16 * 8  * 40 * 40 * 4];
__device__ uint32_t g_s2[16 * 8  * 20 * 20 * 4];
__device__ uint32_t g_s3[16 * 16 * 20 * 20 * 4];
__device__ uint32_t g_s4[16 * 16 * 10 * 10 * 4];
__device__ uint32_t g_s5[16 * 3200 * 4];
__device__ uint32_t g_sb[16 * 128 * 100];           // c-major words per (n,t)
__device__ uint8_t  g_cp0[16 * 42 * 42 * 128];      // input c-major 2-bit bytes (padded)
__device__ uint8_t  g_cp1[16 * 22 * 22 * 128];
__device__ uint16_t g_cp2[16 * 12 * 12 * 128];
__device__ __nv_bfloat16 g_wh[3 * 512 * 3200];      // FC W bf16 splits
__device__ __nv_bfloat16 g_wc2[3 * 80 * 16];        // conv2 taps, 3-split, [s][k][o]
__device__ __nv_bfloat16 g_wc3[3 * 144 * 32];       // conv3 taps, 3-split, [s][k][o]
__device__ float    g_dp2[2 * 16 * 512 * 128];      // fc partials (2 c-halves)

// ---------------------------------------------------------------------------
// K0: pack raw float spikes -> bit words
// ---------------------------------------------------------------------------
__global__ void k_pack(const float* __restrict__ sp) {
    int idx = blockIdx.x * blockDim.x + threadIdx.x;
    const float4* p = (const float4*)(sp + (size_t)idx * 128);
    uint32_t w[4];
#pragma unroll
    for (int j = 0; j < 4; j++) {
        uint32_t b = 0;
#pragma unroll
        for (int q = 0; q < 8; q++) {
            float4 v = p[j * 8 + q];
            b |= (v.x > 0.5f ? 1u : 0u) << (q * 4 + 0);
            b |= (v.y > 0.5f ? 1u : 0u) << (q * 4 + 1);
            b |= (v.z > 0.5f ? 1u : 0u) << (q * 4 + 2);
            b |= (v.w > 0.5f ? 1u : 0u) << (q * 4 + 3);
        }
        w[j] = b;
    }
    *((uint4*)&g_s0[(size_t)idx * 4]) = make_uint4(w[0], w[1], w[2], w[3]);
}

// ---------------------------------------------------------------------------
// K_wsplit: FC W fp32 -> 3 bf16 splits
// ---------------------------------------------------------------------------
__global__ void k_wsplit(const float* __restrict__ W) {
    int i = blockIdx.x * blockDim.x + threadIdx.x;
    float a = W[2 * i], b = W[2 * i + 1];
    __nv_bfloat16 ha = __float2bfloat16(a), hb = __float2bfloat16(b);
    float ra = a - __bfloat162float(ha), rb = b - __bfloat162float(hb);
    __nv_bfloat16 ma = __float2bfloat16(ra), mb = __float2bfloat16(rb);
    float sa = ra - __bfloat162float(ma), sb = rb - __bfloat162float(mb);
    __nv_bfloat16 la = __float2bfloat16(sa), lb = __float2bfloat16(sb);
    uint32_t* g = (uint32_t*)g_wh;
    uint16_t uha = *(uint16_t*)&ha, uhb = *(uint16_t*)&hb;
    uint16_t uma = *(uint16_t*)&ma, umb = *(uint16_t*)&mb;
    uint16_t ula = *(uint16_t*)&la, ulb = *(uint16_t*)&lb;
    g[i]              = (uint32_t)uha | ((uint32_t)uhb << 16);
    g[819200 + i]     = (uint32_t)uma | ((uint32_t)umb << 16);
    g[2 * 819200 + i] = (uint32_t)ula | ((uint32_t)ulb << 16);
}

// ---------------------------------------------------------------------------
// K_wcs: conv2/conv3 taps -> 3-split bf16 B matrices [s][k][o] (scaled x100)
// ---------------------------------------------------------------------------
__global__ void k_wcs(const float* __restrict__ c2w, const float* __restrict__ c3w) {
    int idx = blockIdx.x * blockDim.x + threadIdx.x;   // 5888 useful
    float val = 0.f;
    __nv_bfloat16* dst0;
    int stride;
    if (idx < 80 * 16) {
        int k = idx / 16, o = idx % 16;
        if (k < 72) val = c2w[(o * 8 + (k & 7)) * 9 + (k >> 3)] * 100.0f;
        dst0 = g_wc2 + k * 16 + o;
        stride = 80 * 16;
    } else if (idx < 80 * 16 + 144 * 32) {
        int i2 = idx - 80 * 16;
        int k = i2 / 32, o = i2 % 32;
        val = c3w[(o * 16 + (k & 15)) * 9 + (k >> 4)] * 100.0f;
        dst0 = g_wc3 + k * 32 + o;
        stride = 144 * 32;
    } else return;
    __nv_bfloat16 hi = __float2bfloat16(val);
    float r1 = val - __bfloat162float(hi);
    __nv_bfloat16 md = __float2bfloat16(r1);
    float r2 = r1 - __bfloat162float(md);
    __nv_bfloat16 lo = __float2bfloat16(r2);
    dst0[0] = hi;
    dst0[stride] = md;
    dst0[2 * stride] = lo;
}

// ---------------------------------------------------------------------------
// K_tr2: input bits -> c-major 2-bit bytes, padded 42x42
// ---------------------------------------------------------------------------
__global__ void k_tr2() {
    int i = blockIdx.x * blockDim.x + threadIdx.x;
    int n = i / 6400;
    int r = i % 6400;
    int px = r >> 2, j = r & 3;
    uint32_t w0 = g_s0[((size_t)((n * 2 + 0) * 1600 + px)) * 4 + j];
    uint32_t w1 = g_s0[((size_t)((n * 2 + 1) * 1600 + px)) * 4 + j];
    int h = px / 40, w = px % 40;
    uint8_t* dst = g_cp0 + ((size_t)n * 1764 + (h + 1) * 42 + (w + 1)) * 128 + j * 32;
#pragma unroll
    for (int k = 0; k < 32; k += 4) {
        uint32_t v = 0;
#pragma unroll
        for (int q = 0; q < 4; q++) {
            uint32_t byte = ((w0 >> (k + q)) & 1u) | (((w1 >> (k + q)) & 1u) << 1);
            v |= byte << (q * 8);
        }
        *(uint32_t*)(dst + k) = v;
    }
}

// ---------------------------------------------------------------------------
// K1: sparse conv1 (R11, measured 45.9us) + LIF -> g_s1 (delayed)
// ---------------------------------------------------------------------------
__global__ void __launch_bounds__(128) k_conv1s(const float* __restrict__ wsrc) {
    __shared__ float4   shW4[18 * 2];
    __shared__ uint32_t shTW[128];
    __shared__ float    pre[8 * 129];
    int px = blockIdx.x, n = blockIdx.y;
    int h = px / 40, w = px % 40;
    int tid = threadIdx.x;

    if (tid < 36) {
        int q = tid & 1, tap = tid >> 1;
        int c = tap & 1, dydx = tap >> 1;
        float4 v;
        v.x = wsrc[((4 * q + 0) * 2 + c) * 9 + dydx] * 20.0f;
        v.y = wsrc[((4 * q + 1) * 2 + c) * 9 + dydx] * 20.0f;
        v.z = wsrc[((4 * q + 2) * 2 + c) * 9 + dydx] * 20.0f;
        v.w = wsrc[((4 * q + 3) * 2 + c) * 9 + dydx] * 20.0f;
        shW4[tap * 2 + q] = v;
    }
    {
        const uint8_t* base = g_cp0 + ((size_t)n * 1764 + h * 42 + w) * 128 + tid;
        uint32_t word = 0;
#pragma unroll
        for (int dy = 0; dy < 3; dy++)
#pragma unroll
            for (int dx = 0; dx < 3; dx++)
                word |= (uint32_t)base[(dy * 42 + dx) * 128] << ((dy * 3 + dx) * 2);
        shTW[tid] = word;
    }
    __syncthreads();

    int q = tid & 1, tq = tid >> 1;
#pragma unroll
    for (int i = 0; i < 2; i++) {
        int t = tq * 2 + i;
        uint32_t s = shTW[t];
        unsigned long long a0 = 0ull, a1 = 0ull;
        while (s) {
            int k = __ffs(s) - 1; s &= s - 1;
            const ulonglong2 wv = *(const ulonglong2*)&shW4[k * 2 + q];
            add2(a0, wv.x); add2(a1, wv.y);
        }
        float2 f0 = u64f2(a0), f1 = u64f2(a1);
        pre[(4 * q + 0) * 129 + t] = f0.x;
        pre[(4 * q + 1) * 129 + t] = f0.y;
        pre[(4 * q + 2) * 129 + t] = f1.x;
        pre[(4 * q + 3) * 129 + t] = f1.y;
    }
    __syncthreads();

    if (tid < 8) {
        float u = 0.f, v = 0.f;
        uint32_t ow[4];
#pragma unroll
        for (int j = 0; j < 4; j++) {
            uint32_t bits = 0;
#pragma unroll
            for (int k = 0; k < 32; k++) {
                u = AI * u + pre[tid * 129 + j * 32 + k];
                v = AV * v + u;
                if (v >= TH) { bits |= 1u << k; v = 0.f; }
            }
            ow[j] = bits;
        }
        uint32_t d0 = ow[0] << 1;
        uint32_t d1 = (ow[1] << 1) | (ow[0] >> 31);
        uint32_t d2 = (ow[2] << 1) | (ow[1] >> 31);
        uint32_t d3 = (ow[3] << 1) | (ow[2] >> 31);
        *((uint4*)&g_s1[((((size_t)(n * 8 + tid) * 40 + h) * 40 + w)) * 4]) =
            make_uint4(d0, d1, d2, d3);
    }
}

// ---------------------------------------------------------------------------
// K2: 2x2 sum pool + LIF -> out (delayed)
// ---------------------------------------------------------------------------
__global__ void k_pool(const uint32_t* __restrict__ in, uint32_t* __restrict__ out,
                       int C, int Hin, const float* __restrict__ pw) {
    int Ho = Hin / 2;
    int idx = blockIdx.x * blockDim.x + threadIdx.x;
    int pwi = idx % Ho;
    int t = idx / Ho;
    int phi = t % Ho; t /= Ho;
    int c = t % C;
    int n = t / C;
    float scale = pw[0];

    const uint32_t* b00 = &in[((((n * C + c) * Hin + 2 * phi) * Hin) + 2 * pwi) * 4];
    const uint32_t* b10 = b00 + Hin * 4;

    float u = 0.f, v = 0.f;
    uint32_t ow[4];
#pragma unroll
    for (int j = 0; j < 4; j++) {
        uint32_t a = b00[j], bb = b00[4 + j], cc = b10[j], d = b10[4 + j];
        uint32_t bits = 0;
#pragma unroll
        for (int k = 0; k < 32; k++) {
            int cnt = (int)((a >> k) & 1u) + (int)((bb >> k) & 1u)
                    + (int)((cc >> k) & 1u) + (int)((d >> k) & 1u);
            float x = (float)cnt * scale;
            u = AI * u + x;
            v = AV * v + u;
            if (v >= TH) { bits |= 1u << k; v = 0.f; }
        }
        ow[j] = bits;
    }
    uint32_t d0 = ow[0] << 1;
    uint32_t d1 = (ow[1] << 1) | (ow[0] >> 31);
    uint32_t d2 = (ow[2] << 1) | (ow[1] >> 31);
    uint32_t d3 = (ow[3] << 1) | (ow[2] >> 31);
    *((uint4*)&out[(size_t)idx * 4]) = make_uint4(d0, d1, d2, d3);
}

// ---------------------------------------------------------------------------
// K2b/K4b: c-major transposes (conv inputs)
// ---------------------------------------------------------------------------
__global__ void k_tr8() {
    int i = blockIdx.x * blockDim.x + threadIdx.x;
    int n = i / 1600;
    int r = i % 1600;
    int px = r >> 2, j = r & 3;
    uint32_t wc[8];
#pragma unroll
    for (int c = 0; c < 8; c++)
        wc[c] = g_s2[((size_t)((n * 8 + c) * 400 + px)) * 4 + j];
    int h = px / 20, w = px % 20;
    uint8_t* dst = g_cp1 + ((size_t)n * 484 + (h + 1) * 22 + (w + 1)) * 128 + j * 32;
#pragma unroll
    for (int k = 0; k < 32; k += 4) {
        uint32_t v = 0;
#pragma unroll
        for (int q = 0; q < 4; q++) {
            uint32_t byte = 0;
#pragma unroll
            for (int c = 0; c < 8; c++)
                byte |= ((wc[c] >> (k + q)) & 1u) << c;
            v |= byte << (q * 8);
        }
        *(uint32_t*)(dst + k) = v;
    }
}

__global__ void k_tr16() {
    int i = blockIdx.x * blockDim.x + threadIdx.x;
    int n = i / 400;
    int r = i % 400;
    int px = r >> 2, j = r & 3;
    uint32_t wc[16];
#pragma unroll
    for (int c = 0; c < 16; c++)
        wc[c] = g_s4[((size_t)((n * 16 + c) * 100 + px)) * 4 + j];
    int h = px / 10, w = px % 10;
    uint16_t* dst = g_cp2 + ((size_t)n * 144 + (h + 1) * 12 + (w + 1)) * 128 + j * 32;
#pragma unroll
    for (int k = 0; k < 32; k += 2) {
        uint32_t v = 0;
#pragma unroll
        for (int c = 0; c < 16; c++) {
            v |= ((wc[c] >> k) & 1u) << c;
            v |= ((wc[c] >> (k + 1)) & 1u) << (16 + c);
        }
        *(uint32_t*)(dst + k) = v;
    }
}

// ---------------------------------------------------------------------------
// K_cgemm: per-(pixel, n) WMMA conv + fused LIF. Block 128 thr, 3 syncs.
// D[128 t][COUT] = A[128 t][K taps] (bf16 0/1) . B[K][COUT] (3-split taps).
// MODE 0: conv2  CIN8  H20 COUT16 K80  (taps 72, padded), g_cp1 -> g_s3
// MODE 1: conv3  CIN16 H10 COUT32 K144,                  g_cp2 -> g_s5
// smem: [sA | sB]; sD (fp32) aliases sA after mma completes.
// ---------------------------------------------------------------------------
template <int MODE>
__global__ void __launch_bounds__(128) k_cgemm() {
    constexpr int H     = MODE ? 10 : 20;
    constexpr int PADW  = MODE ? 12 : 22;
    constexpr int COUT  = MODE ? 32 : 16;
    constexpr int K     = MODE ? 144 : 80;
    constexpr int PITCH = MODE ? 152 : 88;      // bf16 elements per A row
    constexpr int ASZ   = 128 * PITCH * 2;      // bytes
    constexpr int BN4   = 3 * K * COUT / 2;     // sB u32 count

    extern __shared__ __align__(16) char smc[];
    __nv_bfloat16* sA = (__nv_bfloat16*)smc;
    float*         sD = (float*)smc;            // alias after mma
    __nv_bfloat16* sB = (__nv_bfloat16*)(smc + ASZ);

    int px = blockIdx.x, n = blockIdx.y;
    int h = px / H, w = px % H;
    int tid = threadIdx.x;
    int warp = tid >> 5;

    // stage B (precomputed 3-split taps)
    {
        const uint32_t* src = (const uint32_t*)(MODE ? g_wc3 : g_wc2);
        uint32_t* dst = (uint32_t*)sB;
        for (int i = tid; i < BN4; i += 128) dst[i] = src[i];
    }
    // stage A: thread = t, expand 9 tap groups to bf16
    {
        uint32_t* rowA = (uint32_t*)sA + tid * (PITCH / 2);
        if (MODE == 0) {
            const uint8_t* base = g_cp0;  // placeholder to keep types; real below
            base = g_cp1 + ((size_t)n * 484 + h * 22 + w) * 128 + tid;
            rowA[36] = 0; rowA[37] = 0; rowA[38] = 0; rowA[39] = 0;  // taps 72..79
#pragma unroll
            for (int dy = 0; dy < 3; dy++)
#pragma unroll
                for (int dx = 0; dx < 3; dx++) {
                    uint32_t b = base[(dy * PADW + dx) * 128];
                    uint32_t* d = rowA + (dy * 3 + dx) * 4;
#pragma unroll
                    for (int q = 0; q < 4; q++) d[q] = expand2(b >> (2 * q));
                }
        } else {
            const uint16_t* base = g_cp2 + ((size_t)n * 144 + h * 12 + w) * 128 + tid;
#pragma unroll
            for (int dy = 0; dy < 3; dy++)
#pragma unroll
                for (int dx = 0; dx < 3; dx++) {
                    uint32_t b = base[(dy * PADW + dx) * 128];
                    uint32_t* d = rowA + (dy * 3 + dx) * 8;
#pragma unroll
                    for (int q = 0; q < 8; q++) d[q] = expand2(b >> (2 * q));
                }
        }
    }
    __syncthreads();

    // mma: 8 row-tiles x (COUT/16) col-tiles, 4 warps
    constexpr int CT = COUT / 16;
    constexpr int KF = K / 16;
    wmma::fragment<wmma::accumulator, 16, 16, 16, float> acc[2][CT];
#pragma unroll
    for (int r = 0; r < 2; r++)
#pragma unroll
        for (int c = 0; c < CT; c++)
            wmma::fill_fragment(acc[r][c], 0.0f);

    for (int s = 0; s < 3; s++) {
#pragma unroll
        for (int kf = 0; kf < KF; kf++) {
            wmma::fragment<wmma::matrix_a, 16, 16, 16, __nv_bfloat16,
                           wmma::row_major> af[2];
            wmma::fragment<wmma::matrix_b, 16, 16, 16, __nv_bfloat16,
                           wmma::row_major> bf[CT];
#pragma unroll
            for (int r = 0; r < 2; r++)
                wmma::load_matrix_sync(af[r],
                    sA + (warp * 2 + r) * 16 * PITCH + kf * 16, PITCH);
#pragma unroll
            for (int c = 0; c < CT; c++)
                wmma::load_matrix_sync(bf[c],
                    sB + (s * K + kf * 16) * COUT + c * 16, COUT);
#pragma unroll
            for (int r = 0; r < 2; r++)
#pragma unroll
                for (int c = 0; c < CT; c++)
                    wmma::mma_sync(acc[r][c], af[r], bf[c], acc[r][c]);
        }
    }
    __syncthreads();   // all sA reads complete before D overwrites

#pragma unroll
    for (int r = 0; r < 2; r++)
#pragma unroll
        for (int c = 0; c < CT; c++)
            wmma::store_matrix_sync(
                sD + (warp * 2 + r) * 16 * COUT + c * 16,
                acc[r][c], COUT, wmma::mem_row_major);
    __syncthreads();

    // LIF epilogue: thread o < COUT, serial over t, delayed bit emit
    if (tid < COUT) {
        int o = tid;
        float u = 0.f, v = 0.f;
        uint32_t ow[4];
#pragma unroll
        for (int j = 0; j < 4; j++) {
            uint32_t bits = 0;
#pragma unroll
            for (int k = 0; k < 32; k++) {
                u = AI * u + sD[(j * 32 + k) * COUT + o];
                v = AV * v + u;
                if (v >= TH) { bits |= 1u << k; v = 0.f; }
            }
            ow[j] = bits;
        }
        uint32_t d0 = ow[0] << 1;
        uint32_t d1 = (ow[1] << 1) | (ow[0] >> 31);
        uint32_t d2 = (ow[2] << 1) | (ow[1] >> 31);
        uint32_t d3 = (ow[3] << 1) | (ow[2] >> 31);
        if (MODE == 0)
            *((uint4*)&g_s3[((size_t)((n * 16 + o) * 400 + px)) * 4]) =
                make_uint4(d0, d1, d2, d3);
        else
            *((uint4*)&g_s5[((size_t)(n * 3200 + o * 100 + px)) * 4]) =
                make_uint4(d0, d1, d2, d3);
    }
}

// ---------------------------------------------------------------------------
// K5b: bit transpose t-major -> c-major (FC input)
// ---------------------------------------------------------------------------
__global__ void k_trans() {
    int gw = (blockIdx.x * blockDim.x + threadIdx.x) >> 5;
    int lane = threadIdx.x & 31;
    int n = gw / 400;
    int r = gw % 400;
    int cw = r >> 2;
    int j = r & 3;
    uint32_t w = g_s5[((size_t)n * 3200 + cw * 32 + lane) * 4 + j];
    uint32_t out = 0;
#pragma unroll
    for (int b = 0; b < 32; b++) {
        uint32_t bl = __ballot_sync(0xffffffffu, (w >> b) & 1u);
        if (lane == b) out = bl;
    }
    g_sb[((size_t)n * 128 + j * 32 + lane) * 100 + cw] = out;
}

// ---------------------------------------------------------------------------
// K_fcw: WMMA bf16 FC (R8 proven). grid (4 ot, 16 n, 2 cs), block 256.
// ---------------------------------------------------------------------------
__global__ void __launch_bounds__(256) k_fcw(float* __restrict__ dp) {
    extern __shared__ __align__(16) __nv_bfloat16 sm[];
    __nv_bfloat16* sA = sm;              // [128][136]
    __nv_bfloat16* sB = sm + 128 * 136;  // [128][136]

    int ot = blockIdx.x, n = blockIdx.y, cs = blockIdx.z;
    int tid = threadIdx.x;
    int warp = tid >> 5;
    int wy = warp >> 2, wx = warp & 3;

    int cbeg = cs ? 13 : 0;
    int cend = cs ? 25 : 13;

    wmma::fragment<wmma::accumulator, 16, 16, 16, float> acc[4][2];
#pragma unroll
    for (int i = 0; i < 4; i++)
#pragma unroll
        for (int j = 0; j < 2; j++)
            wmma::fill_fragment(acc[i][j], 0.0f);

    for (int cc = cbeg; cc < cend; cc++) {
        __syncthreads();
        {
            int t = tid >> 1, half = tid & 1;
            const uint32_t* src = g_sb + ((size_t)n * 128 + t) * 100 + cc * 4 + half * 2;
            uint32_t w0 = src[0], w1 = src[1];
            uint32_t* d32 = (uint32_t*)(sB + t * 136 + half * 64);
#pragma unroll
            for (int b = 0; b < 16; b++)
                d32[b] = (((w0 >> (2 * b)) & 1u) ? 0x3F80u : 0u)
                       | (((w0 >> (2 * b + 1)) & 1u) ? 0x3F800000u : 0u);
#pragma unroll
            for (int b = 0; b < 16; b++)
                d32[16 + b] = (((w1 >> (2 * b)) & 1u) ? 0x3F80u : 0u)
                            | (((w1 >> (2 * b + 1)) & 1u) ? 0x3F800000u : 0u);
        }

        for (int s = 0; s < 3; s++) {
            if (s > 0) __syncthreads();
            {
                const uint4* src = (const uint4*)
                    (g_wh + ((size_t)s * 512 + ot * 128) * 3200 + cc * 128);
#pragma unroll
                for (int r8 = 0; r8 < 8; r8++) {
                    int i = tid + r8 * 256;
                    int r = i >> 4, q2 = i & 15;
                    uint4 v = src[(size_t)r * 400 + q2];
                    *(uint4*)&sA[r * 136 + q2 * 8] = v;
                }
            }
            __syncthreads();

#pragma unroll
            for (int k8 = 0; k8 < 8; k8++) {
                wmma::fragment<wmma::matrix_a, 16, 16, 16, __nv_bfloat16,
                               wmma::row_major> af[4];
                wmma::fragment<wmma::matrix_b, 16, 16, 16, __nv_bfloat16,
                               wmma::col_major> bf[2];
#pragma unroll
                for (int i = 0; i < 4; i++)
                    wmma::load_matrix_sync(af[i],
                        sA + (wy * 64 + i * 16) * 136 + k8 * 16, 136);
#pragma unroll
                for (int j = 0; j < 2; j++)
                    wmma::load_matrix_sync(bf[j],
                        sB + (wx * 32 + j * 16) * 136 + k8 * 16, 136);
#pragma unroll
                for (int i = 0; i < 4; i++)
#pragma unroll
                    for (int j = 0; j < 2; j++)
                        wmma::mma_sync(acc[i][j], af[i], bf[j], acc[i][j]);
            }
        }
    }

    float* base = dp + ((size_t)(cs * 16 + n) * 512 + ot * 128) * 128;
#pragma unroll
    for (int i = 0; i < 4; i++)
#pragma unroll
        for (int j = 0; j < 2; j++)
            wmma::store_matrix_sync(
                base + (wy * 64 + i * 16) * 128 + wx * 32 + j * 16,
                acc[i][j], 128, wmma::mem_row_major);
}

// ---------------------------------------------------------------------------
// K_lif2: sum 2 partials + LIF + output delay-shift -> d_out
// ---------------------------------------------------------------------------
__global__ void k_lif2(float* __restrict__ out) {
    const size_t S = (size_t)16 * 512 * 128;
    int idx = blockIdx.x * blockDim.x + threadIdx.x;
    const float* a = &g_dp2[(size_t)idx * 128];
    float* op = &out[(size_t)idx * 128];
    float u = 0.f, v = 0.f, prev = 0.f;
#pragma unroll 8
    for (int t = 0; t < 128; t++) {
        op[t] = prev;
        float x = a[t] + a[t + S];
        u = AI * u + x;
        v = AV * v + u;
        if (v >= TH) { prev = 1.f; v = 0.f; } else { prev = 0.f; }
    }
}

// ---------------------------------------------------------------------------
extern "C" void kernel_launch(void* const* d_in, const int* in_sizes, int n_in,
                              void* d_out, int out_size) {
    const float* spike = (const float*)d_in[0];
    const float* c1w   = (const float*)d_in[1];
    const float* c2w   = (const float*)d_in[2];
    const float* c3w   = (const float*)d_in[3];
    const float* p1w   = (const float*)d_in[4];
    const float* p2w   = (const float*)d_in[5];
    const float* fcw   = (const float*)d_in[6];
    float* out = (float*)d_out;

    uint32_t *s1, *s2, *s3, *s4;
    float* dp;
    cudaGetSymbolAddress((void**)&s1, g_s1);
    cudaGetSymbolAddress((void**)&s2, g_s2);
    cudaGetSymbolAddress((void**)&s3, g_s3);
    cudaGetSymbolAddress((void**)&s4, g_s4);
    cudaGetSymbolAddress((void**)&dp, g_dp2);

    const int FCW_SMEM = 2 * 128 * 136 * 2;            // 69632 B
    const int C2_SMEM  = 128 * 88 * 2 + 3 * 80 * 16 * 2;    // 22528 + 7680 = 30208
    const int C3_SMEM  = 128 * 152 * 2 + 3 * 144 * 32 * 2;  // 38912 + 27648 = 66560
    cudaFuncSetAttribute((const void*)k_fcw,
                         cudaFuncAttributeMaxDynamicSharedMemorySize, FCW_SMEM);
    cudaFuncSetAttribute((const void*)k_cgemm<0>,
                         cudaFuncAttributeMaxDynamicSharedMemorySize, C2_SMEM);
    cudaFuncSetAttribute((const void*)k_cgemm<1>,
                         cudaFuncAttributeMaxDynamicSharedMemorySize, C3_SMEM);

    k_pack<<<200, 256>>>(spike);
    k_wsplit<<<3200, 256>>>(fcw);                      // FC W -> 3 bf16 splits
    k_wcs<<<23, 256>>>(c2w, c3w);                      // conv taps -> 3-split B
    k_tr2<<<400, 256>>>();
    k_conv1s<<<dim3(1600, 16), 128>>>(c1w);            // sparse conv1 -> g_s1
    k_pool<<<200, 256>>>(s1, s2, 8, 40, p1w);
    k_tr8<<<100, 256>>>();
    k_cgemm<0><<<dim3(400, 16), 128, C2_SMEM>>>();     // conv2 WMMA -> g_s3
    k_pool<<<100, 256>>>(s3, s4, 16, 20, p2w);
    k_tr16<<<25, 256>>>();
    k_cgemm<1><<<dim3(100, 16), 128, C3_SMEM>>>();     // conv3 WMMA -> g_s5
    k_trans<<<800, 256>>>();
    k_fcw<<<dim3(4, 16, 2), 256, FCW_SMEM>>>(dp);      // WMMA bf16 FC
    k_lif2<<<32, 256>>>(out);
}

// round 13
// speedup vs baseline: 1.2397x; 1.2397x over previous
#include <cuda_runtime.h>
#include <cuda_bf16.h>
#include <mma.h>
#include <stdint.h>

using namespace nvcuda;

// Loihi CUBA constants
#define AI 0.75f
#define AV 0.96875f
#define TH 100.0f

__device__ __forceinline__ void add2(unsigned long long& a, unsigned long long b) {
    asm("add.rn.f32x2 %0, %0, %1;" : "+l"(a) : "l"(b));
}
__device__ __forceinline__ float2 u64f2(unsigned long long v) {
    float2 f; asm("mov.b64 {%0, %1}, %2;" : "=f"(f.x), "=f"(f.y) : "l"(v)); return f;
}

// ---------------------------------------------------------------------------
// Buffers (bit k of word j = spike at t = j*32+k; all streams pre-delayed)
// ---------------------------------------------------------------------------
__device__ uint32_t g_s0[16 * 2  * 40 * 40 * 4];
__device__ uint32_t g_s2[16 * 8  * 20 * 20 * 4];
__device__ uint32_t g_s3[16 * 16 * 20 * 20 * 4];
__device__ uint32_t g_s4[16 * 16 * 10 * 10 * 4];
__device__ uint32_t g_s5[16 * 3200 * 4];
__device__ uint32_t g_sb[16 * 128 * 100];           // c-major words per (n,t)
__device__ uint8_t  g_cp1[16 * 22 * 22 * 128];
__device__ uint16_t g_cp2[16 * 12 * 12 * 128];
__device__ __nv_bfloat16 g_wh[3 * 512 * 3200];      // FC W bf16 splits
__device__ float    g_dp2[2 * 16 * 512 * 128];      // fc partials (2 c-halves)

// ---------------------------------------------------------------------------
// K0: pack raw float spikes -> bit words
// ---------------------------------------------------------------------------
__global__ void k_pack(const float* __restrict__ sp) {
    int idx = blockIdx.x * blockDim.x + threadIdx.x;
    const float4* p = (const float4*)(sp + (size_t)idx * 128);
    uint32_t w[4];
#pragma unroll
    for (int j = 0; j < 4; j++) {
        uint32_t b = 0;
#pragma unroll
        for (int q = 0; q < 8; q++) {
            float4 v = p[j * 8 + q];
            b |= (v.x > 0.5f ? 1u : 0u) << (q * 4 + 0);
            b |= (v.y > 0.5f ? 1u : 0u) << (q * 4 + 1);
            b |= (v.z > 0.5f ? 1u : 0u) << (q * 4 + 2);
            b |= (v.w > 0.5f ? 1u : 0u) << (q * 4 + 3);
        }
        w[j] = b;
    }
    *((uint4*)&g_s0[(size_t)idx * 4]) = make_uint4(w[0], w[1], w[2], w[3]);
}

// ---------------------------------------------------------------------------
// K_wsplit: FC W fp32 -> 3 bf16 splits (hi, mid, lo)
// ---------------------------------------------------------------------------
__global__ void k_wsplit(const float* __restrict__ W) {
    int i = blockIdx.x * blockDim.x + threadIdx.x;
    float a = W[2 * i], b = W[2 * i + 1];
    __nv_bfloat16 ha = __float2bfloat16(a), hb = __float2bfloat16(b);
    float ra = a - __bfloat162float(ha), rb = b - __bfloat162float(hb);
    __nv_bfloat16 ma = __float2bfloat16(ra), mb = __float2bfloat16(rb);
    float sa = ra - __bfloat162float(ma), sb = rb - __bfloat162float(mb);
    __nv_bfloat16 la = __float2bfloat16(sa), lb = __float2bfloat16(sb);
    uint32_t* g = (uint32_t*)g_wh;
    uint16_t uha = *(uint16_t*)&ha, uhb = *(uint16_t*)&hb;
    uint16_t uma = *(uint16_t*)&ma, umb = *(uint16_t*)&mb;
    uint16_t ula = *(uint16_t*)&la, ulb = *(uint16_t*)&lb;
    g[i]              = (uint32_t)uha | ((uint32_t)uhb << 16);
    g[819200 + i]     = (uint32_t)uma | ((uint32_t)umb << 16);
    g[2 * 819200 + i] = (uint32_t)ula | ((uint32_t)ulb << 16);
}

// ---------------------------------------------------------------------------
// K_c1p: FUSED conv1 (2->8, w*20) + LIF + delay + 2x2 sum-pool + LIF + delay.
// Block = (n, ph): conv rows h = 2ph, 2ph+1 (640 thr = 2 rows x 40 w x 8 o),
// then pool row ph on 160 threads (pw, c). Writes g_s2 only.
// Numerics identical to the separate conv1 + pool kernels.
// ---------------------------------------------------------------------------
__global__ void __launch_bounds__(640) k_c1p(const float* __restrict__ cw,
                                             const float* __restrict__ pws) {
    __shared__ uint32_t sh[2 * 4 * 42 * 4];   // [c][win row 0..3][wx][j]
    __shared__ uint32_t sd[2 * 40 * 8 * 4];   // delayed conv words [r][w][o][j]
    int b = blockIdx.x;
    int n = b / 20, ph = b % 20;
    int tid = threadIdx.x;

    for (int i = tid; i < 2 * 4 * 42 * 4; i += 640) {
        int j = i & 3;
        int t2 = i >> 2;
        int wx = t2 % 42;
        int t3 = t2 / 42;
        int row = t3 % 4;              // window rows: h = 2ph-1 .. 2ph+2
        int c = t3 / 4;
        int hh = 2 * ph - 1 + row, ws = wx - 1;
        uint32_t v = 0;
        if (hh >= 0 && hh < 40 && ws >= 0 && ws < 40)
            v = g_s0[(((n * 2 + c) * 40 + hh) * 40 + ws) * 4 + j];
        sh[((c * 4 + row) * 42 + wx) * 4 + j] = v;
    }
    __syncthreads();

    {   // conv phase: thread = (r, w, o)
        int r = tid / 320;
        int rt = tid % 320;
        int w = rt % 40, o = rt / 40;
        float wg[18];
#pragma unroll
        for (int i = 0; i < 18; i++) wg[i] = cw[o * 18 + i] * 20.0f;

        float u = 0.f, v = 0.f;
        uint32_t ow[4];
#pragma unroll
        for (int j = 0; j < 4; j++) {
            float acc[32];
#pragma unroll
            for (int k = 0; k < 32; k++) acc[k] = 0.f;
#pragma unroll
            for (int c = 0; c < 2; c++)
#pragma unroll
            for (int dy = 0; dy < 3; dy++)
#pragma unroll
            for (int dx = 0; dx < 3; dx++) {
                uint32_t wd = sh[((c * 4 + (r + dy)) * 42 + (w + dx)) * 4 + j];
                float wt = wg[c * 9 + dy * 3 + dx];
#pragma unroll
                for (int k = 0; k < 32; k++)
                    if (wd & (1u << k)) acc[k] += wt;
            }
            uint32_t bits = 0;
#pragma unroll
            for (int k = 0; k < 32; k++) {
                u = AI * u + acc[k];
                v = AV * v + u;
                if (v >= TH) { bits |= 1u << k; v = 0.f; }
            }
            ow[j] = bits;
        }
        int sdi = ((r * 40 + w) * 8 + o) * 4;
        sd[sdi + 0] = ow[0] << 1;
        sd[sdi + 1] = (ow[1] << 1) | (ow[0] >> 31);
        sd[sdi + 2] = (ow[2] << 1) | (ow[1] >> 31);
        sd[sdi + 3] = (ow[3] << 1) | (ow[2] >> 31);
    }
    __syncthreads();

    // pool phase: thread = (pw, c), 160 active
    if (tid < 160) {
        int pw_ = tid % 20, c = tid / 20;
        float scale = pws[0];
        const uint32_t* p00 = &sd[((0 * 40 + 2 * pw_) * 8 + c) * 4];
        const uint32_t* p01 = &sd[((0 * 40 + 2 * pw_ + 1) * 8 + c) * 4];
        const uint32_t* p10 = &sd[((1 * 40 + 2 * pw_) * 8 + c) * 4];
        const uint32_t* p11 = &sd[((1 * 40 + 2 * pw_ + 1) * 8 + c) * 4];

        float u = 0.f, v = 0.f;
        uint32_t ow[4];
#pragma unroll
        for (int j = 0; j < 4; j++) {
            uint32_t a = p00[j], bb = p01[j], cc = p10[j], d = p11[j];
            uint32_t bits = 0;
#pragma unroll
            for (int k = 0; k < 32; k++) {
                int cnt = (int)((a >> k) & 1u) + (int)((bb >> k) & 1u)
                        + (int)((cc >> k) & 1u) + (int)((d >> k) & 1u);
                float x = (float)cnt * scale;
                u = AI * u + x;
                v = AV * v + u;
                if (v >= TH) { bits |= 1u << k; v = 0.f; }
            }
            ow[j] = bits;
        }
        uint32_t d0 = ow[0] << 1;
        uint32_t d1 = (ow[1] << 1) | (ow[0] >> 31);
        uint32_t d2 = (ow[2] << 1) | (ow[1] >> 31);
        uint32_t d3 = (ow[3] << 1) | (ow[2] >> 31);
        size_t idx = (((size_t)(n * 8 + c) * 20 + ph) * 20 + pw_);
        *((uint4*)&g_s2[idx * 4]) = make_uint4(d0, d1, d2, d3);
    }
}

// ---------------------------------------------------------------------------
// K2: 2x2 sum pool + LIF -> out (delayed). (pool2 only now)
// ---------------------------------------------------------------------------
__global__ void k_pool(const uint32_t* __restrict__ in, uint32_t* __restrict__ out,
                       int C, int Hin, const float* __restrict__ pw) {
    int Ho = Hin / 2;
    int idx = blockIdx.x * blockDim.x + threadIdx.x;
    int pwi = idx % Ho;
    int t = idx / Ho;
    int phi = t % Ho; t /= Ho;
    int c = t % C;
    int n = t / C;
    float scale = pw[0];

    const uint32_t* b00 = &in[((((n * C + c) * Hin + 2 * phi) * Hin) + 2 * pwi) * 4];
    const uint32_t* b10 = b00 + Hin * 4;

    float u = 0.f, v = 0.f;
    uint32_t ow[4];
#pragma unroll
    for (int j = 0; j < 4; j++) {
        uint32_t a = b00[j], bb = b00[4 + j], cc = b10[j], d = b10[4 + j];
        uint32_t bits = 0;
#pragma unroll
        for (int k = 0; k < 32; k++) {
            int cnt = (int)((a >> k) & 1u) + (int)((bb >> k) & 1u)
                    + (int)((cc >> k) & 1u) + (int)((d >> k) & 1u);
            float x = (float)cnt * scale;
            u = AI * u + x;
            v = AV * v + u;
            if (v >= TH) { bits |= 1u << k; v = 0.f; }
        }
        ow[j] = bits;
    }
    uint32_t d0 = ow[0] << 1;
    uint32_t d1 = (ow[1] << 1) | (ow[0] >> 31);
    uint32_t d2 = (ow[2] << 1) | (ow[1] >> 31);
    uint32_t d3 = (ow[3] << 1) | (ow[2] >> 31);
    *((uint4*)&out[(size_t)idx * 4]) = make_uint4(d0, d1, d2, d3);
}

// ---------------------------------------------------------------------------
// K2b/K4b: c-major transposes (conv inputs)
// ---------------------------------------------------------------------------
__global__ void k_tr8() {
    int i = blockIdx.x * blockDim.x + threadIdx.x;
    int n = i / 1600;
    int r = i % 1600;
    int px = r >> 2, j = r & 3;
    uint32_t wc[8];
#pragma unroll
    for (int c = 0; c < 8; c++)
        wc[c] = g_s2[((size_t)((n * 8 + c) * 400 + px)) * 4 + j];
    int h = px / 20, w = px % 20;
    uint8_t* dst = g_cp1 + ((size_t)n * 484 + (h + 1) * 22 + (w + 1)) * 128 + j * 32;
#pragma unroll
    for (int k = 0; k < 32; k += 4) {
        uint32_t v = 0;
#pragma unroll
        for (int q = 0; q < 4; q++) {
            uint32_t byte = 0;
#pragma unroll
            for (int c = 0; c < 8; c++)
                byte |= ((wc[c] >> (k + q)) & 1u) << c;
            v |= byte << (q * 8);
        }
        *(uint32_t*)(dst + k) = v;
    }
}

__global__ void k_tr16() {
    int i = blockIdx.x * blockDim.x + threadIdx.x;
    int n = i / 400;
    int r = i % 400;
    int px = r >> 2, j = r & 3;
    uint32_t wc[16];
#pragma unroll
    for (int c = 0; c < 16; c++)
        wc[c] = g_s4[((size_t)((n * 16 + c) * 100 + px)) * 4 + j];
    int h = px / 10, w = px % 10;
    uint16_t* dst = g_cp2 + ((size_t)n * 144 + (h + 1) * 12 + (w + 1)) * 128 + j * 32;
#pragma unroll
    for (int k = 0; k < 32; k += 2) {
        uint32_t v = 0;
#pragma unroll
        for (int c = 0; c < 16; c++) {
            v |= ((wc[c] >> k) & 1u) << c;
            v |= ((wc[c] >> (k + 1)) & 1u) << (16 + c);
        }
        *(uint32_t*)(dst + k) = v;
    }
}

// ---------------------------------------------------------------------------
// K3: sparse conv2 o-quad (R5, proven)
// ---------------------------------------------------------------------------
__global__ void __launch_bounds__(128) k_conv2s(const float* __restrict__ wsrc) {
    __shared__ float4   shW4[72 * 4];
    __shared__ uint32_t shTW[128 * 3];
    __shared__ float    pre[16 * 129];
    int px = blockIdx.x, n = blockIdx.y;
    int h = px / 20, w = px % 20;
    int tid = threadIdx.x;

    for (int i = tid; i < 72 * 4; i += 128) {
        int q = i & 3, tap = i >> 2;
        int c = tap & 7, dydx = tap >> 3;
        float4 v;
        v.x = wsrc[((4 * q + 0) * 8 + c) * 9 + dydx] * 100.0f;
        v.y = wsrc[((4 * q + 1) * 8 + c) * 9 + dydx] * 100.0f;
        v.z = wsrc[((4 * q + 2) * 8 + c) * 9 + dydx] * 100.0f;
        v.w = wsrc[((4 * q + 3) * 8 + c) * 9 + dydx] * 100.0f;
        shW4[i] = v;
    }
    {
        const uint8_t* base = g_cp1 + ((size_t)n * 484 + h * 22 + w) * 128 + tid;
        uint32_t b[9];
#pragma unroll
        for (int dy = 0; dy < 3; dy++)
#pragma unroll
            for (int dx = 0; dx < 3; dx++)
                b[dy * 3 + dx] = base[(dy * 22 + dx) * 128];
        shTW[tid * 3 + 0] = b[0] | (b[1] << 8) | (b[2] << 16) | (b[3] << 24);
        shTW[tid * 3 + 1] = b[4] | (b[5] << 8) | (b[6] << 16) | (b[7] << 24);
        shTW[tid * 3 + 2] = b[8];
    }
    __syncthreads();

    int q = tid & 3, tq = tid >> 2;
#pragma unroll
    for (int i = 0; i < 4; i++) {
        int t = tq * 4 + i;
        uint32_t s0 = shTW[t * 3], s1 = shTW[t * 3 + 1], s2 = shTW[t * 3 + 2];
        unsigned long long a0 = 0ull, a1 = 0ull;
        while (s0) {
            int k = __ffs(s0) - 1; s0 &= s0 - 1;
            const ulonglong2 wv = *(const ulonglong2*)&shW4[k * 4 + q];
            add2(a0, wv.x); add2(a1, wv.y);
        }
        while (s1) {
            int k = __ffs(s1) - 1; s1 &= s1 - 1;
            const ulonglong2 wv = *(const ulonglong2*)&shW4[(32 + k) * 4 + q];
            add2(a0, wv.x); add2(a1, wv.y);
        }
        while (s2) {
            int k = __ffs(s2) - 1; s2 &= s2 - 1;
            const ulonglong2 wv = *(const ulonglong2*)&shW4[(64 + k) * 4 + q];
            add2(a0, wv.x); add2(a1, wv.y);
        }
        float2 f0 = u64f2(a0), f1 = u64f2(a1);
        pre[(4 * q + 0) * 129 + t] = f0.x;
        pre[(4 * q + 1) * 129 + t] = f0.y;
        pre[(4 * q + 2) * 129 + t] = f1.x;
        pre[(4 * q + 3) * 129 + t] = f1.y;
    }
    __syncthreads();

    if (tid < 16) {
        float u = 0.f, v = 0.f;
        uint32_t ow[4];
#pragma unroll
        for (int j = 0; j < 4; j++) {
            uint32_t bits = 0;
#pragma unroll
            for (int k = 0; k < 32; k++) {
                u = AI * u + pre[tid * 129 + j * 32 + k];
                v = AV * v + u;
                if (v >= TH) { bits |= 1u << k; v = 0.f; }
            }
            ow[j] = bits;
        }
        uint32_t d0 = ow[0] << 1;
        uint32_t d1 = (ow[1] << 1) | (ow[0] >> 31);
        uint32_t d2 = (ow[2] << 1) | (ow[1] >> 31);
        uint32_t d3 = (ow[3] << 1) | (ow[2] >> 31);
        *((uint4*)&g_s3[((size_t)((n * 16 + tid) * 400 + px)) * 4]) =
            make_uint4(d0, d1, d2, d3);
    }
}

// ---------------------------------------------------------------------------
// K5: sparse conv3 o-quad (R5, proven)
// ---------------------------------------------------------------------------
__global__ void __launch_bounds__(128) k_conv3s(const float* __restrict__ wsrc) {
    __shared__ float4   shW4[144 * 8];
    __shared__ uint32_t shTW[128 * 5];
    __shared__ float    pre[32 * 129];
    int px = blockIdx.x, n = blockIdx.y;
    int h = px / 10, w = px % 10;
    int tid = threadIdx.x;

    for (int i = tid; i < 144 * 8; i += 128) {
        int q = i & 7, tap = i >> 3;
        int c = tap & 15, dydx = tap >> 4;
        float4 v;
        v.x = wsrc[((4 * q + 0) * 16 + c) * 9 + dydx] * 100.0f;
        v.y = wsrc[((4 * q + 1) * 16 + c) * 9 + dydx] * 100.0f;
        v.z = wsrc[((4 * q + 2) * 16 + c) * 9 + dydx] * 100.0f;
        v.w = wsrc[((4 * q + 3) * 16 + c) * 9 + dydx] * 100.0f;
        shW4[i] = v;
    }
    {
        const uint16_t* base = g_cp2 + ((size_t)n * 144 + h * 12 + w) * 128 + tid;
        uint32_t b[9];
#pragma unroll
        for (int dy = 0; dy < 3; dy++)
#pragma unroll
            for (int dx = 0; dx < 3; dx++)
                b[dy * 3 + dx] = base[(dy * 12 + dx) * 128];
        shTW[tid * 5 + 0] = b[0] | (b[1] << 16);
        shTW[tid * 5 + 1] = b[2] | (b[3] << 16);
        shTW[tid * 5 + 2] = b[4] | (b[5] << 16);
        shTW[tid * 5 + 3] = b[6] | (b[7] << 16);
        shTW[tid * 5 + 4] = b[8];
    }
    __syncthreads();

    int q = tid & 7, tq = tid >> 3;
#pragma unroll
    for (int i = 0; i < 8; i++) {
        int t = tq * 8 + i;
        unsigned long long a0 = 0ull, a1 = 0ull;
#pragma unroll
        for (int m = 0; m < 5; m++) {
            uint32_t s = shTW[t * 5 + m];
            while (s) {
                int k = __ffs(s) - 1; s &= s - 1;
                const ulonglong2 wv = *(const ulonglong2*)&shW4[(m * 32 + k) * 8 + q];
                add2(a0, wv.x); add2(a1, wv.y);
            }
        }
        float2 f0 = u64f2(a0), f1 = u64f2(a1);
        pre[(4 * q + 0) * 129 + t] = f0.x;
        pre[(4 * q + 1) * 129 + t] = f0.y;
        pre[(4 * q + 2) * 129 + t] = f1.x;
        pre[(4 * q + 3) * 129 + t] = f1.y;
    }
    __syncthreads();

    if (tid < 32) {
        float u = 0.f, v = 0.f;
        uint32_t ow[4];
#pragma unroll
        for (int j = 0; j < 4; j++) {
            uint32_t bits = 0;
#pragma unroll
            for (int k = 0; k < 32; k++) {
                u = AI * u + pre[tid * 129 + j * 32 + k];
                v = AV * v + u;
                if (v >= TH) { bits |= 1u << k; v = 0.f; }
            }
            ow[j] = bits;
        }
        uint32_t d0 = ow[0] << 1;
        uint32_t d1 = (ow[1] << 1) | (ow[0] >> 31);
        uint32_t d2 = (ow[2] << 1) | (ow[1] >> 31);
        uint32_t d3 = (ow[3] << 1) | (ow[2] >> 31);
        *((uint4*)&g_s5[((size_t)(n * 3200 + tid * 100 + px)) * 4]) =
            make_uint4(d0, d1, d2, d3);
    }
}

// ---------------------------------------------------------------------------
// K5b: bit transpose t-major -> c-major (FC input)
// ---------------------------------------------------------------------------
__global__ void k_trans() {
    int gw = (blockIdx.x * blockDim.x + threadIdx.x) >> 5;
    int lane = threadIdx.x & 31;
    int n = gw / 400;
    int r = gw % 400;
    int cw = r >> 2;
    int j = r & 3;
    uint32_t w = g_s5[((size_t)n * 3200 + cw * 32 + lane) * 4 + j];
    uint32_t out = 0;
#pragma unroll
    for (int b = 0; b < 32; b++) {
        uint32_t bl = __ballot_sync(0xffffffffu, (w >> b) & 1u);
        if (lane == b) out = bl;
    }
    g_sb[((size_t)n * 128 + j * 32 + lane) * 100 + cw] = out;
}

// ---------------------------------------------------------------------------
// K_fcw: WMMA bf16 FC. grid (4 ot, 16 n, 2 cs), block 256 = 8 warps.
// All 3 A-splits staged at once (139KB smem, 1 block/SM) -> 2 syncs/chunk
// instead of 4; accumulation order (cc, s, k8) identical to round 8.
// ---------------------------------------------------------------------------
__global__ void __launch_bounds__(256) k_fcw(float* __restrict__ dp) {
    constexpr int SPLT = 128 * 136;
    extern __shared__ __align__(16) __nv_bfloat16 sm[];
    __nv_bfloat16* sA = sm;              // 3 x [128][136]
    __nv_bfloat16* sB = sm + 3 * SPLT;   // [128][136]

    int ot = blockIdx.x, n = blockIdx.y, cs = blockIdx.z;
    int tid = threadIdx.x;
    int warp = tid >> 5;
    int wy = warp >> 2, wx = warp & 3;

    int cbeg = cs ? 13 : 0;
    int cend = cs ? 25 : 13;

    wmma::fragment<wmma::accumulator, 16, 16, 16, float> acc[4][2];
#pragma unroll
    for (int i = 0; i < 4; i++)
#pragma unroll
        for (int j = 0; j < 2; j++)
            wmma::fill_fragment(acc[i][j], 0.0f);

    for (int cc = cbeg; cc < cend; cc++) {
        __syncthreads();   // previous chunk's mma reads done
        // stage B [128 t][128 c] from bit words
        {
            int t = tid >> 1, half = tid & 1;
            const uint32_t* src = g_sb + ((size_t)n * 128 + t) * 100 + cc * 4 + half * 2;
            uint32_t w0 = src[0], w1 = src[1];
            uint32_t* d32 = (uint32_t*)(sB + t * 136 + half * 64);
#pragma unroll
            for (int b = 0; b < 16; b++)
                d32[b] = (((w0 >> (2 * b)) & 1u) ? 0x3F80u : 0u)
                       | (((w0 >> (2 * b + 1)) & 1u) ? 0x3F800000u : 0u);
#pragma unroll
            for (int b = 0; b < 16; b++)
                d32[16 + b] = (((w1 >> (2 * b)) & 1u) ? 0x3F80u : 0u)
                            | (((w1 >> (2 * b + 1)) & 1u) ? 0x3F800000u : 0u);
        }
        // stage all 3 A splits
#pragma unroll
        for (int s = 0; s < 3; s++) {
            const uint4* src = (const uint4*)
                (g_wh + ((size_t)s * 512 + ot * 128) * 3200 + cc * 128);
#pragma unroll
            for (int r8 = 0; r8 < 8; r8++) {
                int i = tid + r8 * 256;
                int r = i >> 4, q2 = i & 15;
                uint4 v = src[(size_t)r * 400 + q2];
                *(uint4*)&sA[s * SPLT + r * 136 + q2 * 8] = v;
            }
        }
        __syncthreads();

        for (int s = 0; s < 3; s++) {
#pragma unroll
            for (int k8 = 0; k8 < 8; k8++) {
                wmma::fragment<wmma::matrix_a, 16, 16, 16, __nv_bfloat16,
                               wmma::row_major> af[4];
                wmma::fragment<wmma::matrix_b, 16, 16, 16, __nv_bfloat16,
                               wmma::col_major> bf[2];
#pragma unroll
                for (int i = 0; i < 4; i++)
                    wmma::load_matrix_sync(af[i],
                        sA + s * SPLT + (wy * 64 + i * 16) * 136 + k8 * 16, 136);
#pragma unroll
                for (int j = 0; j < 2; j++)
                    wmma::load_matrix_sync(bf[j],
                        sB + (wx * 32 + j * 16) * 136 + k8 * 16, 136);
#pragma unroll
                for (int i = 0; i < 4; i++)
#pragma unroll
                    for (int j = 0; j < 2; j++)
                        wmma::mma_sync(acc[i][j], af[i], bf[j], acc[i][j]);
            }
        }
    }

    float* base = dp + ((size_t)(cs * 16 + n) * 512 + ot * 128) * 128;
#pragma unroll
    for (int i = 0; i < 4; i++)
#pragma unroll
        for (int j = 0; j < 2; j++)
            wmma::store_matrix_sync(
                base + (wy * 64 + i * 16) * 128 + wx * 32 + j * 16,
                acc[i][j], 128, wmma::mem_row_major);
}

// ---------------------------------------------------------------------------
// K_lif2: sum 2 partials + LIF + output delay-shift -> d_out
// ---------------------------------------------------------------------------
__global__ void k_lif2(float* __restrict__ out) {
    const size_t S = (size_t)16 * 512 * 128;
    int idx = blockIdx.x * blockDim.x + threadIdx.x;
    const float* a = &g_dp2[(size_t)idx * 128];
    float* op = &out[(size_t)idx * 128];
    float u = 0.f, v = 0.f, prev = 0.f;
#pragma unroll 8
    for (int t = 0; t < 128; t++) {
        op[t] = prev;
        float x = a[t] + a[t + S];
        u = AI * u + x;
        v = AV * v + u;
        if (v >= TH) { prev = 1.f; v = 0.f; } else { prev = 0.f; }
    }
}

// ---------------------------------------------------------------------------
extern "C" void kernel_launch(void* const* d_in, const int* in_sizes, int n_in,
                              void* d_out, int out_size) {
    const float* spike = (const float*)d_in[0];
    const float* c1w   = (const float*)d_in[1];
    const float* c2w   = (const float*)d_in[2];
    const float* c3w   = (const float*)d_in[3];
    const float* p1w   = (const float*)d_in[4];
    const float* p2w   = (const float*)d_in[5];
    const float* fcw   = (const float*)d_in[6];
    float* out = (float*)d_out;

    uint32_t *s3, *s4;
    float* dp;
    cudaGetSymbolAddress((void**)&s3, g_s3);
    cudaGetSymbolAddress((void**)&s4, g_s4);
    cudaGetSymbolAddress((void**)&dp, g_dp2);

    const int FCW_SMEM = 4 * 128 * 136 * 2;   // 139264 B (3 A splits + B)
    cudaFuncSetAttribute((const void*)k_fcw,
                         cudaFuncAttributeMaxDynamicSharedMemorySize, FCW_SMEM);

    k_pack<<<200, 256>>>(spike);
    k_wsplit<<<3200, 256>>>(fcw);                      // FC W -> 3 bf16 splits
    k_c1p<<<320, 640>>>(c1w, p1w);                     // fused conv1+pool1 -> g_s2
    k_tr8<<<100, 256>>>();
    k_conv2s<<<dim3(400, 16), 128>>>(c2w);
    k_pool<<<100, 256>>>(s3, s4, 16, 20, p2w);         // pool2 -> g_s4
    k_tr16<<<25, 256>>>();
    k_conv3s<<<dim3(100, 16), 128>>>(c3w);
    k_trans<<<800, 256>>>();
    k_fcw<<<dim3(4, 16, 2), 256, FCW_SMEM>>>(dp);      // WMMA bf16 FC
    k_lif2<<<32, 256>>>(out);
}

// round 14
// speedup vs baseline: 1.2573x; 1.0143x over previous
#include <cuda_runtime.h>
#include <cuda_bf16.h>
#include <mma.h>
#include <stdint.h>

using namespace nvcuda;

// Loihi CUBA constants
#define AI 0.75f
#define AV 0.96875f
#define TH 100.0f

__device__ __forceinline__ void add2(unsigned long long& a, unsigned long long b) {
    asm("add.rn.f32x2 %0, %0, %1;" : "+l"(a) : "l"(b));
}
__device__ __forceinline__ float2 u64f2(unsigned long long v) {
    float2 f; asm("mov.b64 {%0, %1}, %2;" : "=f"(f.x), "=f"(f.y) : "l"(v)); return f;
}

// ---------------------------------------------------------------------------
// Buffers (bit k of word j = spike at t = j*32+k; all streams pre-delayed)
// ---------------------------------------------------------------------------
__device__ uint32_t g_s0[16 * 2  * 40 * 40 * 4];
__device__ uint32_t g_s3[16 * 16 * 20 * 20 * 4];
__device__ uint32_t g_s5[16 * 3200 * 4];
__device__ uint32_t g_sb[16 * 128 * 100];           // c-major words per (n,t)
__device__ uint8_t  g_cp1[16 * 22 * 22 * 128];      // pool1 out, c-major bytes (padded)
__device__ uint16_t g_cp2[16 * 12 * 12 * 128];      // pool2 out, c-major u16 (padded)
__device__ __nv_bfloat16 g_wh[3 * 512 * 3200];      // FC W bf16 splits
__device__ float    g_dp2[2 * 16 * 512 * 128];      // fc partials (2 c-halves)

// ---------------------------------------------------------------------------
// K0: pack raw float spikes -> bit words
// ---------------------------------------------------------------------------
__global__ void k_pack(const float* __restrict__ sp) {
    int idx = blockIdx.x * blockDim.x + threadIdx.x;
    const float4* p = (const float4*)(sp + (size_t)idx * 128);
    uint32_t w[4];
#pragma unroll
    for (int j = 0; j < 4; j++) {
        uint32_t b = 0;
#pragma unroll
        for (int q = 0; q < 8; q++) {
            float4 v = p[j * 8 + q];
            b |= (v.x > 0.5f ? 1u : 0u) << (q * 4 + 0);
            b |= (v.y > 0.5f ? 1u : 0u) << (q * 4 + 1);
            b |= (v.z > 0.5f ? 1u : 0u) << (q * 4 + 2);
            b |= (v.w > 0.5f ? 1u : 0u) << (q * 4 + 3);
        }
        w[j] = b;
    }
    *((uint4*)&g_s0[(size_t)idx * 4]) = make_uint4(w[0], w[1], w[2], w[3]);
}

// ---------------------------------------------------------------------------
// K_wsplit: FC W fp32 -> 3 bf16 splits (hi, mid, lo)
// ---------------------------------------------------------------------------
__global__ void k_wsplit(const float* __restrict__ W) {
    int i = blockIdx.x * blockDim.x + threadIdx.x;
    float a = W[2 * i], b = W[2 * i + 1];
    __nv_bfloat16 ha = __float2bfloat16(a), hb = __float2bfloat16(b);
    float ra = a - __bfloat162float(ha), rb = b - __bfloat162float(hb);
    __nv_bfloat16 ma = __float2bfloat16(ra), mb = __float2bfloat16(rb);
    float sa = ra - __bfloat162float(ma), sb = rb - __bfloat162float(mb);
    __nv_bfloat16 la = __float2bfloat16(sa), lb = __float2bfloat16(sb);
    uint32_t* g = (uint32_t*)g_wh;
    uint16_t uha = *(uint16_t*)&ha, uhb = *(uint16_t*)&hb;
    uint16_t uma = *(uint16_t*)&ma, umb = *(uint16_t*)&mb;
    uint16_t ula = *(uint16_t*)&la, ulb = *(uint16_t*)&lb;
    g[i]              = (uint32_t)uha | ((uint32_t)uhb << 16);
    g[819200 + i]     = (uint32_t)uma | ((uint32_t)umb << 16);
    g[2 * 819200 + i] = (uint32_t)ula | ((uint32_t)ulb << 16);
}

// ---------------------------------------------------------------------------
// K_c1p: FUSED conv1 + LIF + delay + 2x2 pool + LIF + delay + c-major
// transpose. Block = (n, ph), 640 thr. Writes g_cp1 directly (no g_s2/k_tr8).
// Arithmetic identical to round 13's k_c1p + k_tr8 chain.
// ---------------------------------------------------------------------------
__global__ void __launch_bounds__(640) k_c1p(const float* __restrict__ cw,
                                             const float* __restrict__ pws) {
    __shared__ uint32_t sh[2 * 4 * 42 * 4];   // input halo [c][row 0..3][wx][j]
    __shared__ uint32_t sd[2 * 40 * 8 * 4];   // delayed conv words [r][w][o][j]
    __shared__ uint32_t sp[8 * 20 * 4];       // delayed pool words [c][pw][j]
    int b = blockIdx.x;
    int n = b / 20, ph = b % 20;
    int tid = threadIdx.x;

    for (int i = tid; i < 2 * 4 * 42 * 4; i += 640) {
        int j = i & 3;
        int t2 = i >> 2;
        int wx = t2 % 42;
        int t3 = t2 / 42;
        int row = t3 % 4;
        int c = t3 / 4;
        int hh = 2 * ph - 1 + row, ws = wx - 1;
        uint32_t v = 0;
        if (hh >= 0 && hh < 40 && ws >= 0 && ws < 40)
            v = g_s0[(((n * 2 + c) * 40 + hh) * 40 + ws) * 4 + j];
        sh[((c * 4 + row) * 42 + wx) * 4 + j] = v;
    }
    __syncthreads();

    {   // conv phase: thread = (r, w, o)
        int r = tid / 320;
        int rt = tid % 320;
        int w = rt % 40, o = rt / 40;
        float wg[18];
#pragma unroll
        for (int i = 0; i < 18; i++) wg[i] = cw[o * 18 + i] * 20.0f;

        float u = 0.f, v = 0.f;
        uint32_t ow[4];
#pragma unroll
        for (int j = 0; j < 4; j++) {
            float acc[32];
#pragma unroll
            for (int k = 0; k < 32; k++) acc[k] = 0.f;
#pragma unroll
            for (int c = 0; c < 2; c++)
#pragma unroll
            for (int dy = 0; dy < 3; dy++)
#pragma unroll
            for (int dx = 0; dx < 3; dx++) {
                uint32_t wd = sh[((c * 4 + (r + dy)) * 42 + (w + dx)) * 4 + j];
                float wt = wg[c * 9 + dy * 3 + dx];
#pragma unroll
                for (int k = 0; k < 32; k++)
                    if (wd & (1u << k)) acc[k] += wt;
            }
            uint32_t bits = 0;
#pragma unroll
            for (int k = 0; k < 32; k++) {
                u = AI * u + acc[k];
                v = AV * v + u;
                if (v >= TH) { bits |= 1u << k; v = 0.f; }
            }
            ow[j] = bits;
        }
        int sdi = ((r * 40 + w) * 8 + o) * 4;
        sd[sdi + 0] = ow[0] << 1;
        sd[sdi + 1] = (ow[1] << 1) | (ow[0] >> 31);
        sd[sdi + 2] = (ow[2] << 1) | (ow[1] >> 31);
        sd[sdi + 3] = (ow[3] << 1) | (ow[2] >> 31);
    }
    __syncthreads();

    // pool phase: thread = (pw, c), 160 active -> smem sp
    if (tid < 160) {
        int pw_ = tid % 20, c = tid / 20;
        float scale = pws[0];
        const uint32_t* p00 = &sd[((0 * 40 + 2 * pw_) * 8 + c) * 4];
        const uint32_t* p01 = &sd[((0 * 40 + 2 * pw_ + 1) * 8 + c) * 4];
        const uint32_t* p10 = &sd[((1 * 40 + 2 * pw_) * 8 + c) * 4];
        const uint32_t* p11 = &sd[((1 * 40 + 2 * pw_ + 1) * 8 + c) * 4];

        float u = 0.f, v = 0.f;
        uint32_t ow[4];
#pragma unroll
        for (int j = 0; j < 4; j++) {
            uint32_t a = p00[j], bb = p01[j], cc = p10[j], d = p11[j];
            uint32_t bits = 0;
#pragma unroll
            for (int k = 0; k < 32; k++) {
                int cnt = (int)((a >> k) & 1u) + (int)((bb >> k) & 1u)
                        + (int)((cc >> k) & 1u) + (int)((d >> k) & 1u);
                float x = (float)cnt * scale;
                u = AI * u + x;
                v = AV * v + u;
                if (v >= TH) { bits |= 1u << k; v = 0.f; }
            }
            ow[j] = bits;
        }
        sp[(c * 20 + pw_) * 4 + 0] = ow[0] << 1;
        sp[(c * 20 + pw_) * 4 + 1] = (ow[1] << 1) | (ow[0] >> 31);
        sp[(c * 20 + pw_) * 4 + 2] = (ow[2] << 1) | (ow[1] >> 31);
        sp[(c * 20 + pw_) * 4 + 3] = (ow[3] << 1) | (ow[2] >> 31);
    }
    __syncthreads();

    // transpose phase (ex k_tr8): thread = (pw, j), 80 active -> g_cp1 bytes
    if (tid < 80) {
        int pw_ = tid >> 2, j = tid & 3;
        uint32_t wc[8];
#pragma unroll
        for (int c = 0; c < 8; c++)
            wc[c] = sp[(c * 20 + pw_) * 4 + j];
        uint8_t* dst = g_cp1 + ((size_t)n * 484 + (ph + 1) * 22 + (pw_ + 1)) * 128 + j * 32;
#pragma unroll
        for (int k = 0; k < 32; k += 4) {
            uint32_t v = 0;
#pragma unroll
            for (int q = 0; q < 4; q++) {
                uint32_t byte = 0;
#pragma unroll
                for (int c = 0; c < 8; c++)
                    byte |= ((wc[c] >> (k + q)) & 1u) << c;
                v |= byte << (q * 8);
            }
            *(uint32_t*)(dst + k) = v;
        }
    }
}

// ---------------------------------------------------------------------------
// K3: sparse conv2 o-quad (R5, proven) -> g_s3
// ---------------------------------------------------------------------------
__global__ void __launch_bounds__(128) k_conv2s(const float* __restrict__ wsrc) {
    __shared__ float4   shW4[72 * 4];
    __shared__ uint32_t shTW[128 * 3];
    __shared__ float    pre[16 * 129];
    int px = blockIdx.x, n = blockIdx.y;
    int h = px / 20, w = px % 20;
    int tid = threadIdx.x;

    for (int i = tid; i < 72 * 4; i += 128) {
        int q = i & 3, tap = i >> 2;
        int c = tap & 7, dydx = tap >> 3;
        float4 v;
        v.x = wsrc[((4 * q + 0) * 8 + c) * 9 + dydx] * 100.0f;
        v.y = wsrc[((4 * q + 1) * 8 + c) * 9 + dydx] * 100.0f;
        v.z = wsrc[((4 * q + 2) * 8 + c) * 9 + dydx] * 100.0f;
        v.w = wsrc[((4 * q + 3) * 8 + c) * 9 + dydx] * 100.0f;
        shW4[i] = v;
    }
    {
        const uint8_t* base = g_cp1 + ((size_t)n * 484 + h * 22 + w) * 128 + tid;
        uint32_t b[9];
#pragma unroll
        for (int dy = 0; dy < 3; dy++)
#pragma unroll
            for (int dx = 0; dx < 3; dx++)
                b[dy * 3 + dx] = base[(dy * 22 + dx) * 128];
        shTW[tid * 3 + 0] = b[0] | (b[1] << 8) | (b[2] << 16) | (b[3] << 24);
        shTW[tid * 3 + 1] = b[4] | (b[5] << 8) | (b[6] << 16) | (b[7] << 24);
        shTW[tid * 3 + 2] = b[8];
    }
    __syncthreads();

    int q = tid & 3, tq = tid >> 2;
#pragma unroll
    for (int i = 0; i < 4; i++) {
        int t = tq * 4 + i;
        uint32_t s0 = shTW[t * 3], s1 = shTW[t * 3 + 1], s2 = shTW[t * 3 + 2];
        unsigned long long a0 = 0ull, a1 = 0ull;
        while (s0) {
            int k = __ffs(s0) - 1; s0 &= s0 - 1;
            const ulonglong2 wv = *(const ulonglong2*)&shW4[k * 4 + q];
            add2(a0, wv.x); add2(a1, wv.y);
        }
        while (s1) {
            int k = __ffs(s1) - 1; s1 &= s1 - 1;
            const ulonglong2 wv = *(const ulonglong2*)&shW4[(32 + k) * 4 + q];
            add2(a0, wv.x); add2(a1, wv.y);
        }
        while (s2) {
            int k = __ffs(s2) - 1; s2 &= s2 - 1;
            const ulonglong2 wv = *(const ulonglong2*)&shW4[(64 + k) * 4 + q];
            add2(a0, wv.x); add2(a1, wv.y);
        }
        float2 f0 = u64f2(a0), f1 = u64f2(a1);
        pre[(4 * q + 0) * 129 + t] = f0.x;
        pre[(4 * q + 1) * 129 + t] = f0.y;
        pre[(4 * q + 2) * 129 + t] = f1.x;
        pre[(4 * q + 3) * 129 + t] = f1.y;
    }
    __syncthreads();

    if (tid < 16) {
        float u = 0.f, v = 0.f;
        uint32_t ow[4];
#pragma unroll
        for (int j = 0; j < 4; j++) {
            uint32_t bits = 0;
#pragma unroll
            for (int k = 0; k < 32; k++) {
                u = AI * u + pre[tid * 129 + j * 32 + k];
                v = AV * v + u;
                if (v >= TH) { bits |= 1u << k; v = 0.f; }
            }
            ow[j] = bits;
        }
        uint32_t d0 = ow[0] << 1;
        uint32_t d1 = (ow[1] << 1) | (ow[0] >> 31);
        uint32_t d2 = (ow[2] << 1) | (ow[1] >> 31);
        uint32_t d3 = (ow[3] << 1) | (ow[2] >> 31);
        *((uint4*)&g_s3[((size_t)((n * 16 + tid) * 400 + px)) * 4]) =
            make_uint4(d0, d1, d2, d3);
    }
}

// ---------------------------------------------------------------------------
// K_p2t: FUSED pool2 + LIF + delay + c-major u16 transpose -> g_cp2.
// Block = (n, ph), 160 threads (pw=10 x c=16). Arithmetic identical to the
// round-13 k_pool + k_tr16 chain.
// ---------------------------------------------------------------------------
__global__ void __launch_bounds__(160) k_p2t(const float* __restrict__ pws) {
    __shared__ uint32_t sp[16 * 10 * 4];   // delayed pool words [c][pw][j]
    int b = blockIdx.x;
    int n = b / 10, ph = b % 10;
    int tid = threadIdx.x;

    {
        int pw_ = tid % 10, c = tid / 10;
        float scale = pws[0];
        const uint32_t* b00 = &g_s3[((size_t)((n * 16 + c) * 400 + (2 * ph) * 20 + 2 * pw_)) * 4];
        const uint32_t* b10 = b00 + 20 * 4;

        float u = 0.f, v = 0.f;
        uint32_t ow[4];
#pragma unroll
        for (int j = 0; j < 4; j++) {
            uint32_t a = b00[j], bb = b00[4 + j], cc = b10[j], d = b10[4 + j];
            uint32_t bits = 0;
#pragma unroll
            for (int k = 0; k < 32; k++) {
                int cnt = (int)((a >> k) & 1u) + (int)((bb >> k) & 1u)
                        + (int)((cc >> k) & 1u) + (int)((d >> k) & 1u);
                float x = (float)cnt * scale;
                u = AI * u + x;
                v = AV * v + u;
                if (v >= TH) { bits |= 1u << k; v = 0.f; }
            }
            ow[j] = bits;
        }
        sp[(c * 10 + pw_) * 4 + 0] = ow[0] << 1;
        sp[(c * 10 + pw_) * 4 + 1] = (ow[1] << 1) | (ow[0] >> 31);
        sp[(c * 10 + pw_) * 4 + 2] = (ow[2] << 1) | (ow[1] >> 31);
        sp[(c * 10 + pw_) * 4 + 3] = (ow[3] << 1) | (ow[2] >> 31);
    }
    __syncthreads();

    // transpose phase (ex k_tr16): thread = (pw, j), 40 active
    if (tid < 40) {
        int pw_ = tid >> 2, j = tid & 3;
        uint32_t wc[16];
#pragma unroll
        for (int c = 0; c < 16; c++)
            wc[c] = sp[(c * 10 + pw_) * 4 + j];
        uint16_t* dst = g_cp2 + ((size_t)n * 144 + (ph + 1) * 12 + (pw_ + 1)) * 128 + j * 32;
#pragma unroll
        for (int k = 0; k < 32; k += 2) {
            uint32_t v = 0;
#pragma unroll
            for (int c = 0; c < 16; c++) {
                v |= ((wc[c] >> k) & 1u) << c;
                v |= ((wc[c] >> (k + 1)) & 1u) << (16 + c);
            }
            *(uint32_t*)(dst + k) = v;
        }
    }
}

// ---------------------------------------------------------------------------
// K5: sparse conv3 o-quad (R5, proven) -> g_s5
// ---------------------------------------------------------------------------
__global__ void __launch_bounds__(128) k_conv3s(const float* __restrict__ wsrc) {
    __shared__ float4   shW4[144 * 8];
    __shared__ uint32_t shTW[128 * 5];
    __shared__ float    pre[32 * 129];
    int px = blockIdx.x, n = blockIdx.y;
    int h = px / 10, w = px % 10;
    int tid = threadIdx.x;

    for (int i = tid; i < 144 * 8; i += 128) {
        int q = i & 7, tap = i >> 3;
        int c = tap & 15, dydx = tap >> 4;
        float4 v;
        v.x = wsrc[((4 * q + 0) * 16 + c) * 9 + dydx] * 100.0f;
        v.y = wsrc[((4 * q + 1) * 16 + c) * 9 + dydx] * 100.0f;
        v.z = wsrc[((4 * q + 2) * 16 + c) * 9 + dydx] * 100.0f;
        v.w = wsrc[((4 * q + 3) * 16 + c) * 9 + dydx] * 100.0f;
        shW4[i] = v;
    }
    {
        const uint16_t* base = g_cp2 + ((size_t)n * 144 + h * 12 + w) * 128 + tid;
        uint32_t b[9];
#pragma unroll
        for (int dy = 0; dy < 3; dy++)
#pragma unroll
            for (int dx = 0; dx < 3; dx++)
                b[dy * 3 + dx] = base[(dy * 12 + dx) * 128];
        shTW[tid * 5 + 0] = b[0] | (b[1] << 16);
        shTW[tid * 5 + 1] = b[2] | (b[3] << 16);
        shTW[tid * 5 + 2] = b[4] | (b[5] << 16);
        shTW[tid * 5 + 3] = b[6] | (b[7] << 16);
        shTW[tid * 5 + 4] = b[8];
    }
    __syncthreads();

    int q = tid & 7, tq = tid >> 3;
#pragma unroll
    for (int i = 0; i < 8; i++) {
        int t = tq * 8 + i;
        unsigned long long a0 = 0ull, a1 = 0ull;
#pragma unroll
        for (int m = 0; m < 5; m++) {
            uint32_t s = shTW[t * 5 + m];
            while (s) {
                int k = __ffs(s) - 1; s &= s - 1;
                const ulonglong2 wv = *(const ulonglong2*)&shW4[(m * 32 + k) * 8 + q];
                add2(a0, wv.x); add2(a1, wv.y);
            }
        }
        float2 f0 = u64f2(a0), f1 = u64f2(a1);
        pre[(4 * q + 0) * 129 + t] = f0.x;
        pre[(4 * q + 1) * 129 + t] = f0.y;
        pre[(4 * q + 2) * 129 + t] = f1.x;
        pre[(4 * q + 3) * 129 + t] = f1.y;
    }
    __syncthreads();

    if (tid < 32) {
        float u = 0.f, v = 0.f;
        uint32_t ow[4];
#pragma unroll
        for (int j = 0; j < 4; j++) {
            uint32_t bits = 0;
#pragma unroll
            for (int k = 0; k < 32; k++) {
                u = AI * u + pre[tid * 129 + j * 32 + k];
                v = AV * v + u;
                if (v >= TH) { bits |= 1u << k; v = 0.f; }
            }
            ow[j] = bits;
        }
        uint32_t d0 = ow[0] << 1;
        uint32_t d1 = (ow[1] << 1) | (ow[0] >> 31);
        uint32_t d2 = (ow[2] << 1) | (ow[1] >> 31);
        uint32_t d3 = (ow[3] << 1) | (ow[2] >> 31);
        *((uint4*)&g_s5[((size_t)(n * 3200 + tid * 100 + px)) * 4]) =
            make_uint4(d0, d1, d2, d3);
    }
}

// ---------------------------------------------------------------------------
// K5b: bit transpose t-major -> c-major (FC input)
// ---------------------------------------------------------------------------
__global__ void k_trans() {
    int gw = (blockIdx.x * blockDim.x + threadIdx.x) >> 5;
    int lane = threadIdx.x & 31;
    int n = gw / 400;
    int r = gw % 400;
    int cw = r >> 2;
    int j = r & 3;
    uint32_t w = g_s5[((size_t)n * 3200 + cw * 32 + lane) * 4 + j];
    uint32_t out = 0;
#pragma unroll
    for (int b = 0; b < 32; b++) {
        uint32_t bl = __ballot_sync(0xffffffffu, (w >> b) & 1u);
        if (lane == b) out = bl;
    }
    g_sb[((size_t)n * 128 + j * 32 + lane) * 100 + cw] = out;
}

// ---------------------------------------------------------------------------
// K_fcw: WMMA bf16 FC (R13). grid (4 ot, 16 n, 2 cs), block 256.
// ---------------------------------------------------------------------------
__global__ void __launch_bounds__(256) k_fcw(float* __restrict__ dp) {
    constexpr int SPLT = 128 * 136;
    extern __shared__ __align__(16) __nv_bfloat16 sm[];
    __nv_bfloat16* sA = sm;              // 3 x [128][136]
    __nv_bfloat16* sB = sm + 3 * SPLT;   // [128][136]

    int ot = blockIdx.x, n = blockIdx.y, cs = blockIdx.z;
    int tid = threadIdx.x;
    int warp = tid >> 5;
    int wy = warp >> 2, wx = warp & 3;

    int cbeg = cs ? 13 : 0;
    int cend = cs ? 25 : 13;

    wmma::fragment<wmma::accumulator, 16, 16, 16, float> acc[4][2];
#pragma unroll
    for (int i = 0; i < 4; i++)
#pragma unroll
        for (int j = 0; j < 2; j++)
            wmma::fill_fragment(acc[i][j], 0.0f);

    for (int cc = cbeg; cc < cend; cc++) {
        __syncthreads();
        {
            int t = tid >> 1, half = tid & 1;
            const uint32_t* src = g_sb + ((size_t)n * 128 + t) * 100 + cc * 4 + half * 2;
            uint32_t w0 = src[0], w1 = src[1];
            uint32_t* d32 = (uint32_t*)(sB + t * 136 + half * 64);
#pragma unroll
            for (int b = 0; b < 16; b++)
                d32[b] = (((w0 >> (2 * b)) & 1u) ? 0x3F80u : 0u)
                       | (((w0 >> (2 * b + 1)) & 1u) ? 0x3F800000u : 0u);
#pragma unroll
            for (int b = 0; b < 16; b++)
                d32[16 + b] = (((w1 >> (2 * b)) & 1u) ? 0x3F80u : 0u)
                            | (((w1 >> (2 * b + 1)) & 1u) ? 0x3F800000u : 0u);
        }
#pragma unroll
        for (int s = 0; s < 3; s++) {
            const uint4* src = (const uint4*)
                (g_wh + ((size_t)s * 512 + ot * 128) * 3200 + cc * 128);
#pragma unroll
            for (int r8 = 0; r8 < 8; r8++) {
                int i = tid + r8 * 256;
                int r = i >> 4, q2 = i & 15;
                uint4 v = src[(size_t)r * 400 + q2];
                *(uint4*)&sA[s * SPLT + r * 136 + q2 * 8] = v;
            }
        }
        __syncthreads();

        for (int s = 0; s < 3; s++) {
#pragma unroll
            for (int k8 = 0; k8 < 8; k8++) {
                wmma::fragment<wmma::matrix_a, 16, 16, 16, __nv_bfloat16,
                               wmma::row_major> af[4];
                wmma::fragment<wmma::matrix_b, 16, 16, 16, __nv_bfloat16,
                               wmma::col_major> bf[2];
#pragma unroll
                for (int i = 0; i < 4; i++)
                    wmma::load_matrix_sync(af[i],
                        sA + s * SPLT + (wy * 64 + i * 16) * 136 + k8 * 16, 136);
#pragma unroll
                for (int j = 0; j < 2; j++)
                    wmma::load_matrix_sync(bf[j],
                        sB + (wx * 32 + j * 16) * 136 + k8 * 16, 136);
#pragma unroll
                for (int i = 0; i < 4; i++)
#pragma unroll
                    for (int j = 0; j < 2; j++)
                        wmma::mma_sync(acc[i][j], af[i], bf[j], acc[i][j]);
            }
        }
    }

    float* base = dp + ((size_t)(cs * 16 + n) * 512 + ot * 128) * 128;
#pragma unroll
    for (int i = 0; i < 4; i++)
#pragma unroll
        for (int j = 0; j < 2; j++)
            wmma::store_matrix_sync(
                base + (wy * 64 + i * 16) * 128 + wx * 32 + j * 16,
                acc[i][j], 128, wmma::mem_row_major);
}

// ---------------------------------------------------------------------------
// K_lif2: sum 2 partials + LIF + output delay-shift -> d_out
// ---------------------------------------------------------------------------
__global__ void k_lif2(float* __restrict__ out) {
    const size_t S = (size_t)16 * 512 * 128;
    int idx = blockIdx.x * blockDim.x + threadIdx.x;
    const float* a = &g_dp2[(size_t)idx * 128];
    float* op = &out[(size_t)idx * 128];
    float u = 0.f, v = 0.f, prev = 0.f;
#pragma unroll 8
    for (int t = 0; t < 128; t++) {
        op[t] = prev;
        float x = a[t] + a[t + S];
        u = AI * u + x;
        v = AV * v + u;
        if (v >= TH) { prev = 1.f; v = 0.f; } else { prev = 0.f; }
    }
}

// ---------------------------------------------------------------------------
extern "C" void kernel_launch(void* const* d_in, const int* in_sizes, int n_in,
                              void* d_out, int out_size) {
    const float* spike = (const float*)d_in[0];
    const float* c1w   = (const float*)d_in[1];
    const float* c2w   = (const float*)d_in[2];
    const float* c3w   = (const float*)d_in[3];
    const float* p1w   = (const float*)d_in[4];
    const float* p2w   = (const float*)d_in[5];
    const float* fcw   = (const float*)d_in[6];
    float* out = (float*)d_out;

    float* dp;
    cudaGetSymbolAddress((void**)&dp, g_dp2);

    const int FCW_SMEM = 4 * 128 * 136 * 2;   // 139264 B (3 A splits + B)
    cudaFuncSetAttribute((const void*)k_fcw,
                         cudaFuncAttributeMaxDynamicSharedMemorySize, FCW_SMEM);

    k_pack<<<200, 256>>>(spike);
    k_wsplit<<<3200, 256>>>(fcw);                      // FC W -> 3 bf16 splits
    k_c1p<<<320, 640>>>(c1w, p1w);                     // conv1+pool1+tr8 -> g_cp1
    k_conv2s<<<dim3(400, 16), 128>>>(c2w);             // -> g_s3
    k_p2t<<<160, 160>>>(p2w);                          // pool2+tr16 -> g_cp2
    k_conv3s<<<dim3(100, 16), 128>>>(c3w);             // -> g_s5
    k_trans<<<800, 256>>>();                           // -> g_sb
    k_fcw<<<dim3(4, 16, 2), 256, FCW_SMEM>>>(dp);      // WMMA bf16 FC
    k_lif2<<<32, 256>>>(out);
}